// round 2
// baseline (speedup 1.0000x reference)
#include <cuda_runtime.h>
#include <math_constants.h>

#define NMAX 4096
#define WARPS_PER_BLOCK 8
#define BLOCK_THREADS (WARPS_PER_BLOCK * 32)

typedef unsigned long long u64;

// ---- packed f32x2 helpers (Blackwell sm_103a) ----
__device__ __forceinline__ u64 pk2(float a, float b) {
    u64 r; asm("mov.b64 %0, {%1, %2};" : "=l"(r) : "f"(a), "f"(b)); return r;
}
__device__ __forceinline__ void upk2(u64 v, float& a, float& b) {
    asm("mov.b64 {%0, %1}, %2;" : "=f"(a), "=f"(b) : "l"(v));
}
__device__ __forceinline__ u64 add2(u64 a, u64 b) {
    u64 r; asm("add.rn.f32x2 %0, %1, %2;" : "=l"(r) : "l"(a), "l"(b)); return r;
}
__device__ __forceinline__ u64 mul2(u64 a, u64 b) {
    u64 r; asm("mul.rn.f32x2 %0, %1, %2;" : "=l"(r) : "l"(a), "l"(b)); return r;
}
__device__ __forceinline__ u64 fma2(u64 a, u64 b, u64 c) {
    u64 r; asm("fma.rn.f32x2 %0, %1, %2, %3;" : "=l"(r) : "l"(a), "l"(b), "l"(c)); return r;
}

// strict-less insert: within a lane, candidate j's arrive in ascending order,
// so strict < keeps the earlier index on exact ties (matches top_k stability)
#define TRY_INSERT(d2v, jv)                                        \
    do {                                                           \
        if ((d2v) < s1) {                                          \
            s3 = s2; i3 = i2; s2 = s1; i2 = i1;                    \
            if ((d2v) < s0) { s1 = s0; i1 = i0; s0 = (d2v); i0 = (jv); } \
            else            { s1 = (d2v); i1 = (jv); }             \
        } else {                                                   \
            if ((d2v) < s2) { s3 = s2; i3 = i2; s2 = (d2v); i2 = (jv); } \
            else            { s3 = (d2v); i3 = (jv); }             \
        }                                                          \
    } while (0)

// cross-lane merge: interleaved j order between lanes, so equal distances
// must resolve to the smaller index
#define LESSI(da, ja, db, jb) (((da) < (db)) || ((da) == (db) && (ja) < (jb)))
#define MERGE_INSERT(dv, jv)                                       \
    if (LESSI(dv, jv, s3, i3)) {                                   \
        if (LESSI(dv, jv, s1, i1)) {                               \
            s3 = s2; i3 = i2; s2 = s1; i2 = i1;                    \
            if (LESSI(dv, jv, s0, i0)) { s1 = s0; i1 = i0; s0 = (dv); i0 = (jv); } \
            else                       { s1 = (dv); i1 = (jv); }   \
        } else {                                                   \
            if (LESSI(dv, jv, s2, i2)) { s3 = s2; i3 = i2; s2 = (dv); i2 = (jv); } \
            else                       { s3 = (dv); i3 = (jv); }   \
        }                                                          \
    }

__global__ __launch_bounds__(BLOCK_THREADS)
void nn_pool_kernel(const float* __restrict__ obs1,
                    const float* __restrict__ obs2,
                    const float* __restrict__ W,
                    const float* __restrict__ b,
                    float* __restrict__ out,
                    int n)
{
    // SoA layout: x's and y's separate so LDS.128 yields aligned f32x2 pairs
    __shared__ __align__(16) float sx[NMAX];
    __shared__ __align__(16) float sy[NMAX];

    const int tid = threadIdx.x;

    const float2* __restrict__ gpos = (const float2*)obs2;
    for (int t = tid; t < n; t += BLOCK_THREADS) {
        float2 p = gpos[t];
        sx[t] = p.x;
        sy[t] = p.y;
    }
    __syncthreads();

    const int warp = tid >> 5;
    const int lane = tid & 31;
    const int i = blockIdx.x * WARPS_PER_BLOCK + warp;
    if (i >= n) return;

    const float pix = sx[i];
    const float piy = sy[i];
    const u64 npx2 = pk2(-pix, -pix);   // broadcast -pi for packed subtract
    const u64 npy2 = pk2(-piy, -piy);

    float s0 = CUDART_INF_F, s1 = CUDART_INF_F, s2 = CUDART_INF_F, s3 = CUDART_INF_F;
    int   i0 = n, i1 = n, i2 = n, i3 = n;

    // hot loop: lane handles 4 consecutive pairs per iter, j = 4*lane + 128*t.
    // Common path: packed distance math + min-reduce + one compare.
    // Insert (and the j != i self-check) lives only in the rarely-taken branch.
    const int niter = n >> 7;   // n / 128
    for (int t = 0; t < niter; ++t) {
        const int j = 4 * lane + (t << 7);
        float4 xv = *(const float4*)&sx[j];
        float4 yv = *(const float4*)&sy[j];

        u64 dx01 = add2(pk2(xv.x, xv.y), npx2);
        u64 dx23 = add2(pk2(xv.z, xv.w), npx2);
        u64 dy01 = add2(pk2(yv.x, yv.y), npy2);
        u64 dy23 = add2(pk2(yv.z, yv.w), npy2);

        u64 d2p01 = fma2(dx01, dx01, mul2(dy01, dy01));
        u64 d2p23 = fma2(dx23, dx23, mul2(dy23, dy23));

        float d20, d21, d22, d23;
        upk2(d2p01, d20, d21);
        upk2(d2p23, d22, d23);

        float m = fminf(fminf(d20, d21), fminf(d22, d23));
        if (m < s3) {
            // slow path: exact per-candidate check incl. self exclusion
            if (d20 < s3 && (j + 0) != i) TRY_INSERT(d20, j + 0);
            if (d21 < s3 && (j + 1) != i) TRY_INSERT(d21, j + 1);
            if (d22 < s3 && (j + 2) != i) TRY_INSERT(d22, j + 2);
            if (d23 < s3 && (j + 3) != i) TRY_INSERT(d23, j + 3);
        }
    }

    // generic tail (n not a multiple of 128)
    for (int j = (niter << 7) + lane; j < n; j += 32) {
        float dx = sx[j] - pix;
        float dy = sy[j] - piy;
        float d2 = fmaf(dx, dx, dy * dy);
        if (d2 < s3 && j != i) TRY_INSERT(d2, j);
    }

    // butterfly merge: after 5 steps every lane holds the warp-global top-4
    #pragma unroll
    for (int off = 16; off > 0; off >>= 1) {
        float t0 = __shfl_xor_sync(0xffffffffu, s0, off);
        float t1 = __shfl_xor_sync(0xffffffffu, s1, off);
        float t2 = __shfl_xor_sync(0xffffffffu, s2, off);
        float t3 = __shfl_xor_sync(0xffffffffu, s3, off);
        int   u0 = __shfl_xor_sync(0xffffffffu, i0, off);
        int   u1 = __shfl_xor_sync(0xffffffffu, i1, off);
        int   u2 = __shfl_xor_sync(0xffffffffu, i2, off);
        int   u3 = __shfl_xor_sync(0xffffffffu, i3, off);
        MERGE_INSERT(t0, u0);
        MERGE_INSERT(t1, u1);
        MERGE_INSERT(t2, u2);
        MERGE_INSERT(t3, u3);
    }

    // epilogue: lane = k*8 + e computes out[i][k*8 + e]
    const int k = lane >> 3;
    const int e = lane & 7;
    int nj = (k == 0) ? i0 : (k == 1) ? i1 : (k == 2) ? i2 : i3;

    const float2* __restrict__ go1 = (const float2*)obs1;
    float pjx = sx[nj];
    float pjy = sy[nj];
    float2 o1j = go1[nj];
    float2 o1i = go1[i];

    float rpx = pjx - pix;
    float rpy = pjy - piy;
    float rvx = (pjx - o1j.x) - (pix - o1i.x);
    float rvy = (pjy - o1j.y) - (piy - o1i.y);

    float acc = b[e];
    acc = fmaf(rpx, W[0 * 8 + e], acc);
    acc = fmaf(rpy, W[1 * 8 + e], acc);
    acc = fmaf(rvx, W[2 * 8 + e], acc);
    acc = fmaf(rvy, W[3 * 8 + e], acc);

    out[i * 32 + lane] = fmaxf(acc, 0.0f);
}

extern "C" void kernel_launch(void* const* d_in, const int* in_sizes, int n_in,
                              void* d_out, int out_size) {
    const float* obs1 = (const float*)d_in[0];  // [N, 2]
    const float* obs2 = (const float*)d_in[1];  // [N, 2]
    const float* W    = (const float*)d_in[2];  // [4, 8]
    const float* b    = (const float*)d_in[3];  // [8]
    float* out = (float*)d_out;                  // [N, 32]

    int n = in_sizes[0] / 2;
    int blocks = (n + WARPS_PER_BLOCK - 1) / WARPS_PER_BLOCK;
    nn_pool_kernel<<<blocks, BLOCK_THREADS>>>(obs1, obs2, W, b, out, n);
}